// round 4
// baseline (speedup 1.0000x reference)
#include <cuda_runtime.h>

#define Nn 100000
#define Ee 1600000
#define FIN 128
#define K1 129
#define HD 128
#define NCARDS 110
#define STR 132      // padded row stride (16B multiple)
#define KP 144       // padded K rows for transposed weights
#define SCAN_NB 98   // ceil(100000/1024)

typedef unsigned long long u64;

// ---------------- device scratch (no allocs allowed) ----------------
__device__ float g_h0[(size_t)Nn * STR];
__device__ float g_h1[(size_t)Nn * STR];
__device__ float g_h2[(size_t)Nn * STR];
__device__ float g_sum[(size_t)Nn * STR];   // holds MEAN-aggregated features
__device__ float g_WlT[KP * HD];
__device__ float g_WrT[KP * HD];
__device__ float g_Wl2T[KP * HD];
__device__ float g_Wr2T[KP * HD];
__device__ float g_WoT[KP * HD];
__device__ int g_degc[Nn];
__device__ int g_cnt[Nn];
__device__ int g_scan[Nn];
__device__ int g_offs[Nn];
__device__ int g_btot[SCAN_NB];
__device__ int g_boff[SCAN_NB];
__device__ int g_csrc[Ee];
__device__ int g_is64;   // 1 if edge_index buffer is int64, 0 if int32

// ---------------- f32x2 packed-FMA helpers ----------------
__device__ __forceinline__ u64 pk(float a) {
    u64 r; unsigned u = __float_as_uint(a);
    asm("mov.b64 %0, {%1, %1};" : "=l"(r) : "r"(u));
    return r;
}
__device__ __forceinline__ u64 fma2(u64 a, u64 b, u64 c) {
    u64 d;
    asm("fma.rn.f32x2 %0, %1, %2, %3;" : "=l"(d) : "l"(a), "l"(b), "l"(c));
    return d;
}
__device__ __forceinline__ void unpk(u64 v, float& lo, float& hi) {
    unsigned a, b;
    asm("mov.b64 {%0, %1}, %2;" : "=r"(a), "=r"(b) : "l"(v));
    lo = __uint_as_float(a); hi = __uint_as_float(b);
}

// Load edge index element i (array layout [2, Ee] flattened), dtype-agnostic.
__device__ __forceinline__ unsigned load_ei(const int* p, size_t i, int is64) {
    if (is64) return (unsigned)((const long long*)p)[i];
    return (unsigned)p[i];
}

// ---------------- dtype detection ----------------
__global__ void k_detect(const int* __restrict__ ei32) {
    // int64 node indices < 2^31 => every odd 32-bit word (high half) is 0.
    // True int32 indices in [0,100000) make that astronomically unlikely.
    int all_zero = 1;
    for (int w = 1; w < 64; w += 2)
        if (ei32[w] != 0) { all_zero = 0; break; }
    g_is64 = all_zero;
}

// ---------------- setup kernels ----------------
__global__ void k_init() {
    int i = blockIdx.x * blockDim.x + threadIdx.x;
    int stride = gridDim.x * blockDim.x;
    for (int t = i; t < Nn; t += stride) { g_degc[t] = 0; g_cnt[t] = 0; }
}

__global__ void k_prep_w(const float* __restrict__ Wl1, const float* __restrict__ Wr1,
                         const float* __restrict__ Wl2, const float* __restrict__ Wr2,
                         const float* __restrict__ Wo) {
    int i = blockIdx.x * blockDim.x + threadIdx.x;
    if (i >= KP * HD) return;
    int k = i / HD, j = i % HD;
    g_WlT[i]  = (k < K1) ? Wl1[j * K1 + k] : 0.f;
    g_WrT[i]  = (k < K1) ? Wr1[j * K1 + k] : 0.f;
    g_Wl2T[i] = (k < HD) ? Wl2[j * HD + k] : 0.f;
    g_Wr2T[i] = (k < HD) ? Wr2[j * HD + k] : 0.f;
    g_WoT[i]  = (k < HD && j < NCARDS) ? Wo[j * HD + k] : 0.f;
}

__global__ void k_concat(const float* __restrict__ x, const int* __restrict__ cards) {
    int n = blockIdx.x;
    int t = threadIdx.x;  // 128 threads
    g_h0[(size_t)n * STR + t] = x[(size_t)n * FIN + t];
    if (t == 0) {
        g_h0[(size_t)n * STR + 128] = (float)cards[n];
        g_h0[(size_t)n * STR + 129] = 0.f;
        g_h0[(size_t)n * STR + 130] = 0.f;
        g_h0[(size_t)n * STR + 131] = 0.f;
    }
}

// ---------------- CSR build (dtype-agnostic, defensively clamped) ----------------
__global__ void k_deghist(const int* __restrict__ ei) {
    int e = blockIdx.x * blockDim.x + threadIdx.x;
    if (e < Ee) {
        int is64 = g_is64;
        unsigned d = load_ei(ei, (size_t)Ee + e, is64);
        if (d < Nn) atomicAdd(&g_degc[d], 1);
    }
}

__global__ void k_scan1() {
    __shared__ int sh[1024];
    int b = blockIdx.x, t = threadIdx.x;
    int n = b * 1024 + t;
    int v = (n < Nn) ? g_degc[n] : 0;
    sh[t] = v;
    __syncthreads();
    for (int off = 1; off < 1024; off <<= 1) {
        int add = (t >= off) ? sh[t - off] : 0;
        __syncthreads();
        sh[t] += add;
        __syncthreads();
    }
    if (n < Nn) g_scan[n] = sh[t];
    if (t == 1023) g_btot[b] = sh[t];
}

__global__ void k_scan2() {
    __shared__ int sh[128];
    int t = threadIdx.x;
    int v = (t < SCAN_NB) ? g_btot[t] : 0;
    sh[t] = v;
    __syncthreads();
    for (int off = 1; off < 128; off <<= 1) {
        int add = (t >= off) ? sh[t - off] : 0;
        __syncthreads();
        sh[t] += add;
        __syncthreads();
    }
    if (t < SCAN_NB) g_boff[t] = sh[t] - v;  // exclusive block offset
}

__global__ void k_scan3() {
    int n = blockIdx.x * blockDim.x + threadIdx.x;
    if (n < Nn) g_offs[n] = g_scan[n] - g_degc[n] + g_boff[n >> 10];
}

__global__ void k_place(const int* __restrict__ ei) {
    int e = blockIdx.x * blockDim.x + threadIdx.x;
    if (e < Ee) {
        int is64 = g_is64;
        unsigned s = load_ei(ei, (size_t)e, is64);
        unsigned d = load_ei(ei, (size_t)Ee + e, is64);
        if (s < Nn && d < Nn) {
            int pos = g_offs[d] + atomicAdd(&g_cnt[d], 1);
            if (pos >= 0 && pos < Ee) g_csrc[pos] = (int)s;
        }
    }
}

// ---------------- gather mean-aggregation (no float atomics) ----------------
__global__ void k_gather(int layer) {
    const float* __restrict__ h = layer ? g_h1 : g_h0;
    int gw = (blockIdx.x * blockDim.x + threadIdx.x) >> 5;
    int lane = threadIdx.x & 31;
    int nw = (gridDim.x * blockDim.x) >> 5;
    for (int n = gw; n < Nn; n += nw) {
        int st = g_offs[n];
        int dg = g_degc[n];
        if (st < 0) st = 0;
        if (st + dg > Ee) dg = Ee - st;
        float4 acc = make_float4(0.f, 0.f, 0.f, 0.f);
        float accC = 0.f;
        int sNext = (dg > 0) ? g_csrc[st] : 0;
        for (int i = 0; i < dg; ++i) {
            int s = sNext;
            if (i + 1 < dg) sNext = g_csrc[st + i + 1];
            const float* row = h + (size_t)s * STR;
            float4 v = *(const float4*)(row + lane * 4);
            acc.x += v.x; acc.y += v.y; acc.z += v.z; acc.w += v.w;
            if (layer == 0 && lane == 0) accC += row[128];
        }
        float di = (dg > 0) ? 1.f / (float)dg : 0.f;
        acc.x *= di; acc.y *= di; acc.z *= di; acc.w *= di;
        float* orow = g_sum + (size_t)n * STR;
        *(float4*)(orow + lane * 4) = acc;
        if (lane == 0)
            *(float4*)(orow + 128) = make_float4(accC * di, 0.f, 0.f, 0.f);
    }
}

// ---------------- fused SAGE layer: relu(mean@Wl^T + bl + self@Wr^T + br) ----------------
#define BM 64
#define BK 16

__global__ __launch_bounds__(256) void k_layer(const float* __restrict__ bl,
                                               const float* __restrict__ br,
                                               int layer, int K) {
    const float* __restrict__ self_ = layer ? g_h1 : g_h0;
    const float* __restrict__ WTl = layer ? g_Wl2T : g_WlT;
    const float* __restrict__ WTr = layer ? g_Wr2T : g_WrT;
    float* __restrict__ out = layer ? g_h2 : g_h1;

    __shared__ __align__(16) float As[2][BK][BM];
    __shared__ __align__(16) float Bs[2][BK][HD];
    int tid = threadIdx.x;
    int tx = tid & 31;   // output quad: j = tx*4 .. tx*4+3
    int ty = tid >> 5;   // node group: m = ty*8 .. ty*8+7
    int n0 = blockIdx.x * BM;

    u64 acc[8][2];
#pragma unroll
    for (int i = 0; i < 8; i++) { acc[i][0] = 0ULL; acc[i][1] = 0ULL; }

    int nch = (K + BK - 1) / BK;
    int mA = tid & 63, kqA = tid >> 6;

    for (int kc = 0; kc < nch; ++kc) {
        int k0 = kc * BK;
        // A tiles (transposed into smem)
        {
            int n = n0 + mA;
            int kk = k0 + kqA * 4;
            float4 vm = make_float4(0.f, 0.f, 0.f, 0.f);
            float4 vs = vm;
            if (n < Nn && kk < STR) {
                vm = *(const float4*)(g_sum + (size_t)n * STR + kk);
                vs = *(const float4*)(self_ + (size_t)n * STR + kk);
            }
            As[0][kqA * 4 + 0][mA] = vm.x; As[0][kqA * 4 + 1][mA] = vm.y;
            As[0][kqA * 4 + 2][mA] = vm.z; As[0][kqA * 4 + 3][mA] = vm.w;
            As[1][kqA * 4 + 0][mA] = vs.x; As[1][kqA * 4 + 1][mA] = vs.y;
            As[1][kqA * 4 + 2][mA] = vs.z; As[1][kqA * 4 + 3][mA] = vs.w;
        }
        // B tiles (already transposed in global, zero padded beyond K)
#pragma unroll
        for (int f = tid; f < 512; f += 256) {
            int k = f >> 5, jq = f & 31;
            *(float4*)&Bs[0][k][jq * 4] = *(const float4*)(WTl + (size_t)(k0 + k) * HD + jq * 4);
            *(float4*)&Bs[1][k][jq * 4] = *(const float4*)(WTr + (size_t)(k0 + k) * HD + jq * 4);
        }
        __syncthreads();
#pragma unroll
        for (int k = 0; k < BK; ++k) {
            ulonglong2 wlp = *(const ulonglong2*)&Bs[0][k][tx * 4];
            ulonglong2 wrp = *(const ulonglong2*)&Bs[1][k][tx * 4];
            float am[8], ah[8];
            *(float4*)&am[0] = *(const float4*)&As[0][k][ty * 8];
            *(float4*)&am[4] = *(const float4*)&As[0][k][ty * 8 + 4];
            *(float4*)&ah[0] = *(const float4*)&As[1][k][ty * 8];
            *(float4*)&ah[4] = *(const float4*)&As[1][k][ty * 8 + 4];
#pragma unroll
            for (int i = 0; i < 8; i++) {
                u64 a2 = pk(am[i]);
                acc[i][0] = fma2(a2, wlp.x, acc[i][0]);
                acc[i][1] = fma2(a2, wlp.y, acc[i][1]);
                u64 b2 = pk(ah[i]);
                acc[i][0] = fma2(b2, wrp.x, acc[i][0]);
                acc[i][1] = fma2(b2, wrp.y, acc[i][1]);
            }
        }
        __syncthreads();
    }
    float bb[4];
#pragma unroll
    for (int c = 0; c < 4; c++) bb[c] = bl[tx * 4 + c] + br[tx * 4 + c];
#pragma unroll
    for (int i = 0; i < 8; i++) {
        int n = n0 + ty * 8 + i;
        if (n < Nn) {
            float o0, o1, o2, o3;
            unpk(acc[i][0], o0, o1);
            unpk(acc[i][1], o2, o3);
            float4 v;
            v.x = fmaxf(o0 + bb[0], 0.f);
            v.y = fmaxf(o1 + bb[1], 0.f);
            v.z = fmaxf(o2 + bb[2], 0.f);
            v.w = fmaxf(o3 + bb[3], 0.f);
            *(float4*)(out + (size_t)n * STR + tx * 4) = v;
        }
    }
}

// ---------------- output head: h2 @ Wo^T + bo ----------------
__global__ __launch_bounds__(256) void k_out(const float* __restrict__ bo,
                                             float* __restrict__ out) {
    __shared__ __align__(16) float As[BK][BM];
    __shared__ __align__(16) float Bs[BK][HD];
    int tid = threadIdx.x;
    int tx = tid & 31;
    int ty = tid >> 5;
    int n0 = blockIdx.x * BM;

    u64 acc[8][2];
#pragma unroll
    for (int i = 0; i < 8; i++) { acc[i][0] = 0ULL; acc[i][1] = 0ULL; }

    int mA = tid & 63, kqA = tid >> 6;
    for (int kc = 0; kc < HD / BK; ++kc) {
        int k0 = kc * BK;
        {
            int n = n0 + mA;
            int kk = k0 + kqA * 4;
            float4 vs = make_float4(0.f, 0.f, 0.f, 0.f);
            if (n < Nn) vs = *(const float4*)(g_h2 + (size_t)n * STR + kk);
            As[kqA * 4 + 0][mA] = vs.x; As[kqA * 4 + 1][mA] = vs.y;
            As[kqA * 4 + 2][mA] = vs.z; As[kqA * 4 + 3][mA] = vs.w;
        }
#pragma unroll
        for (int f = tid; f < 512; f += 256) {
            int k = f >> 5, jq = f & 31;
            *(float4*)&Bs[k][jq * 4] = *(const float4*)(g_WoT + (size_t)(k0 + k) * HD + jq * 4);
        }
        __syncthreads();
#pragma unroll
        for (int k = 0; k < BK; ++k) {
            ulonglong2 wp = *(const ulonglong2*)&Bs[k][tx * 4];
            float a[8];
            *(float4*)&a[0] = *(const float4*)&As[k][ty * 8];
            *(float4*)&a[4] = *(const float4*)&As[k][ty * 8 + 4];
#pragma unroll
            for (int i = 0; i < 8; i++) {
                u64 a2 = pk(a[i]);
                acc[i][0] = fma2(a2, wp.x, acc[i][0]);
                acc[i][1] = fma2(a2, wp.y, acc[i][1]);
            }
        }
        __syncthreads();
    }
    float bb[4];
#pragma unroll
    for (int c = 0; c < 4; c++) {
        int j = tx * 4 + c;
        bb[c] = (j < NCARDS) ? bo[j] : 0.f;
    }
#pragma unroll
    for (int i = 0; i < 8; i++) {
        int n = n0 + ty * 8 + i;
        if (n < Nn) {
            float o[4];
            unpk(acc[i][0], o[0], o[1]);
            unpk(acc[i][1], o[2], o[3]);
#pragma unroll
            for (int c = 0; c < 4; c++) {
                int j = tx * 4 + c;
                if (j < NCARDS) out[(size_t)n * NCARDS + j] = o[c] + bb[c];
            }
        }
    }
}

// ---------------- launch: identify inputs by element-count signature ----------------
extern "C" void kernel_launch(void* const* d_in, const int* in_sizes, int n_in,
                              void* d_out, int out_size) {
    // defaults = canonical setup_inputs() order (fallback)
    int ix = 0, iWl1 = 1, ibl1 = 2, iWr1 = 3, ibr1 = 4, iWl2 = 5, ibl2 = 6,
        iWr2 = 7, ibr2 = 8, iWo = 9, ibo = 10, iei = 11, icards = 12;
    if (n_in == 13) {
        int w1[2] = {-1, -1}; int n_w1 = 0;
        int w2[2] = {-1, -1}; int n_w2 = 0;
        int bb[4] = {-1, -1, -1, -1}; int n_b = 0;
        int f_x = -1, f_Wo = -1, f_bo = -1, f_ei = -1, f_cards = -1;
        for (int i = 0; i < n_in; i++) {
            switch (in_sizes[i]) {
                case (int)((size_t)Nn * FIN): f_x = i; break;
                case HD * K1: if (n_w1 < 2) w1[n_w1++] = i; break;
                case HD * HD: if (n_w2 < 2) w2[n_w2++] = i; break;
                case HD:      if (n_b < 4)  bb[n_b++]  = i; break;
                case NCARDS * HD: f_Wo = i; break;
                case NCARDS:      f_bo = i; break;
                case 2 * Ee:      f_ei = i; break;
                case Nn:          f_cards = i; break;
                default: break;
            }
        }
        if (f_x >= 0 && n_w1 == 2 && n_w2 == 2 && n_b == 4 && f_Wo >= 0 &&
            f_bo >= 0 && f_ei >= 0 && f_cards >= 0) {
            ix = f_x; iWl1 = w1[0]; iWr1 = w1[1]; iWl2 = w2[0]; iWr2 = w2[1];
            ibl1 = bb[0]; ibr1 = bb[1]; ibl2 = bb[2]; ibr2 = bb[3];
            iWo = f_Wo; ibo = f_bo; iei = f_ei; icards = f_cards;
        }
    }

    const float* x   = (const float*)d_in[ix];
    const float* Wl1 = (const float*)d_in[iWl1];
    const float* bl1 = (const float*)d_in[ibl1];
    const float* Wr1 = (const float*)d_in[iWr1];
    const float* br1 = (const float*)d_in[ibr1];
    const float* Wl2 = (const float*)d_in[iWl2];
    const float* bl2 = (const float*)d_in[ibl2];
    const float* Wr2 = (const float*)d_in[iWr2];
    const float* br2 = (const float*)d_in[ibr2];
    const float* Wo  = (const float*)d_in[iWo];
    const float* bo  = (const float*)d_in[ibo];
    const int* ei    = (const int*)d_in[iei];
    const int* cards = (const int*)d_in[icards];
    float* out = (float*)d_out;

    k_detect<<<1, 1>>>(ei);
    k_init<<<(Nn + 255) / 256, 256>>>();
    k_prep_w<<<(KP * HD + 255) / 256, 256>>>(Wl1, Wr1, Wl2, Wr2, Wo);
    k_concat<<<Nn, 128>>>(x, cards);

    k_deghist<<<(Ee + 255) / 256, 256>>>(ei);
    k_scan1<<<SCAN_NB, 1024>>>();
    k_scan2<<<1, 128>>>();
    k_scan3<<<(Nn + 255) / 256, 256>>>();
    k_place<<<(Ee + 255) / 256, 256>>>(ei);

    k_gather<<<2048, 256>>>(0);
    k_layer<<<(Nn + BM - 1) / BM, 256>>>(bl1, br1, 0, K1);

    k_gather<<<2048, 256>>>(1);
    k_layer<<<(Nn + BM - 1) / BM, 256>>>(bl2, br2, 1, HD);

    k_out<<<(Nn + BM - 1) / BM, 256>>>(bo, out);
}

// round 6
// speedup vs baseline: 1.1538x; 1.1538x over previous
#include <cuda_runtime.h>
#include <cuda_bf16.h>
#include <cstdint>

#define Nn 100000
#define Ee 1600000
#define FIN 128
#define K1 129
#define HD 128
#define NCARDS 110
#define STR 132
#define SCAN_NB 98
#define TILE_M 128
#define NTILES ((Nn + TILE_M - 1) / TILE_M)   // 782

typedef unsigned int u32;

// ---------------- device scratch ----------------
__device__ float g_h0[(size_t)Nn * STR];
__device__ float g_h1[(size_t)Nn * STR];
__device__ float g_h2[(size_t)Nn * STR];
__device__ float g_sum[(size_t)Nn * STR];
// bf16 split weights: op 0=Wl1,1=Wr1,2=Wl2,3=Wr2,4=Wo (padded to [128,128], row-major [n][k])
__device__ __nv_bfloat16 g_Whi[5][HD * HD];
__device__ __nv_bfloat16 g_Wlo[5][HD * HD];
__device__ int g_degc[Nn];
__device__ int g_cnt[Nn];
__device__ int g_scan[Nn];
__device__ int g_offs[Nn];
__device__ int g_btot[SCAN_NB];
__device__ int g_boff[SCAN_NB];
__device__ int g_csrc[Ee];
__device__ int g_is64;

// ---------------- helpers ----------------
__device__ __forceinline__ unsigned load_ei(const int* p, size_t i, int is64) {
    if (is64) return (unsigned)((const long long*)p)[i];
    return (unsigned)p[i];
}
__device__ __forceinline__ uint32_t smem_u32(const void* p) {
    uint32_t a;
    asm("{ .reg .u64 t; cvta.to.shared.u64 t, %1; cvt.u32.u64 %0, t; }" : "=r"(a) : "l"(p));
    return a;
}
__device__ __forceinline__ u32 cvt2(float a, float b) {
    __nv_bfloat162 t = __floats2bfloat162_rn(a, b);
    return *(u32*)&t;
}

#define LDM4(r, addr) \
    asm volatile("ldmatrix.sync.aligned.m8n8.x4.shared.b16 {%0,%1,%2,%3}, [%4];" \
                 : "=r"((r)[0]), "=r"((r)[1]), "=r"((r)[2]), "=r"((r)[3]) : "r"(addr))

#define MMA(c, a, bb0, bb1) \
    asm volatile("mma.sync.aligned.m16n8k16.row.col.f32.bf16.bf16.f32 " \
                 "{%0,%1,%2,%3},{%4,%5,%6,%7},{%8,%9},{%0,%1,%2,%3};" \
                 : "+f"((c)[0]), "+f"((c)[1]), "+f"((c)[2]), "+f"((c)[3]) \
                 : "r"((a)[0]), "r"((a)[1]), "r"((a)[2]), "r"((a)[3]), "r"(bb0), "r"(bb1))

// smem layout (bytes); row stride 272 = 17*16 -> conflict-free ldmatrix
#define RS 272
#define S_AHI 0
#define S_ALO 34816
#define S_WHI 69632
#define S_WLO 104448
#define S_AUX 139264            // bias[128], r1l[128], r1r[128] floats
#define SMEM_DYN (139264 + 3 * 128 * 4)

// ---------------- dtype detection ----------------
__global__ void k_detect(const int* __restrict__ ei32) {
    int all_zero = 1;
    for (int w = 1; w < 64; w += 2)
        if (ei32[w] != 0) { all_zero = 0; break; }
    g_is64 = all_zero;
}

// ---------------- setup ----------------
__global__ void k_init() {
    int i = blockIdx.x * blockDim.x + threadIdx.x;
    if (i < Nn) { g_degc[i] = 0; g_cnt[i] = 0; }
}

__global__ void k_prep_w(const float* __restrict__ Wl1, const float* __restrict__ Wr1,
                         const float* __restrict__ Wl2, const float* __restrict__ Wr2,
                         const float* __restrict__ Wo) {
    int i = blockIdx.x * blockDim.x + threadIdx.x;
    if (i >= 5 * HD * HD) return;
    int op = i / (HD * HD);
    int r = i % (HD * HD);
    int n = r / HD, k = r % HD;
    float v = 0.f;
    if (op == 0) v = Wl1[n * K1 + k];
    else if (op == 1) v = Wr1[n * K1 + k];
    else if (op == 2) v = Wl2[n * HD + k];
    else if (op == 3) v = Wr2[n * HD + k];
    else if (n < NCARDS) v = Wo[n * HD + k];
    __nv_bfloat16 h = __float2bfloat16_rn(v);
    g_Whi[op][r] = h;
    g_Wlo[op][r] = __float2bfloat16_rn(v - __bfloat162float(h));
}

__global__ void k_concat(const float* __restrict__ x, const int* __restrict__ cards) {
    int i = blockIdx.x * blockDim.x + threadIdx.x;
    if (i >= Nn * 32) return;
    int n = i >> 5, c = (i & 31) * 4;
    *(float4*)(g_h0 + (size_t)n * STR + c) = *(const float4*)(x + (size_t)n * FIN + c);
    if ((i & 31) == 0)
        *(float4*)(g_h0 + (size_t)n * STR + 128) = make_float4((float)cards[n], 0.f, 0.f, 0.f);
}

// ---------------- CSR build ----------------
__global__ void k_deghist(const int* __restrict__ ei) {
    int e = blockIdx.x * blockDim.x + threadIdx.x;
    if (e < Ee) {
        unsigned d = load_ei(ei, (size_t)Ee + e, g_is64);
        if (d < Nn) atomicAdd(&g_degc[d], 1);
    }
}

__global__ void k_scan1() {
    __shared__ int sh[1024];
    int b = blockIdx.x, t = threadIdx.x;
    int n = b * 1024 + t;
    int v = (n < Nn) ? g_degc[n] : 0;
    sh[t] = v;
    __syncthreads();
    for (int off = 1; off < 1024; off <<= 1) {
        int add = (t >= off) ? sh[t - off] : 0;
        __syncthreads();
        sh[t] += add;
        __syncthreads();
    }
    if (n < Nn) g_scan[n] = sh[t];
    if (t == 1023) g_btot[b] = sh[t];
}

__global__ void k_scan2() {
    __shared__ int sh[128];
    int t = threadIdx.x;
    int v = (t < SCAN_NB) ? g_btot[t] : 0;
    sh[t] = v;
    __syncthreads();
    for (int off = 1; off < 128; off <<= 1) {
        int add = (t >= off) ? sh[t - off] : 0;
        __syncthreads();
        sh[t] += add;
        __syncthreads();
    }
    if (t < SCAN_NB) g_boff[t] = sh[t] - v;
}

__global__ void k_scan3() {
    int n = blockIdx.x * blockDim.x + threadIdx.x;
    if (n < Nn) g_offs[n] = g_scan[n] - g_degc[n] + g_boff[n >> 10];
}

__global__ void k_place(const int* __restrict__ ei) {
    int e = blockIdx.x * blockDim.x + threadIdx.x;
    if (e < Ee) {
        int is64 = g_is64;
        unsigned s = load_ei(ei, (size_t)e, is64);
        unsigned d = load_ei(ei, (size_t)Ee + e, is64);
        if (s < Nn && d < Nn) {
            int pos = g_offs[d] + atomicAdd(&g_cnt[d], 1);
            if (pos >= 0 && pos < Ee) g_csrc[pos] = (int)s;
        }
    }
}

// ---------------- gather mean-aggregation ----------------
__global__ void k_gather(int layer) {
    const float* __restrict__ h = layer ? g_h1 : g_h0;
    int gw = (blockIdx.x * blockDim.x + threadIdx.x) >> 5;
    int lane = threadIdx.x & 31;
    int nw = (gridDim.x * blockDim.x) >> 5;
    for (int n = gw; n < Nn; n += nw) {
        int st = g_offs[n];
        int dg = g_degc[n];
        if (st < 0) st = 0;
        if (st + dg > Ee) dg = Ee - st;
        float4 acc = make_float4(0.f, 0.f, 0.f, 0.f);
        float accC = 0.f;
        int sNext = (dg > 0) ? g_csrc[st] : 0;
        for (int i = 0; i < dg; ++i) {
            int s = sNext;
            if (i + 1 < dg) sNext = g_csrc[st + i + 1];
            const float* row = h + (size_t)s * STR;
            float4 v = *(const float4*)(row + lane * 4);
            acc.x += v.x; acc.y += v.y; acc.z += v.z; acc.w += v.w;
            if (layer == 0 && lane == 0) accC += row[128];
        }
        float di = (dg > 0) ? 1.f / (float)dg : 0.f;
        acc.x *= di; acc.y *= di; acc.z *= di; acc.w *= di;
        float* orow = g_sum + (size_t)n * STR;
        *(float4*)(orow + lane * 4) = acc;
        if (lane == 0)
            *(float4*)(orow + 128) = make_float4(accC * di, 0.f, 0.f, 0.f);
    }
}

// ---------------- HMMA fused layer ----------------
// out[m][:] = act( sum_ops A_op[m][:] @ W_op^T (+rank1) + biases )
// split precision: D = AhBh + AhBl + AlBh, fp32 accumulate.
__global__ __launch_bounds__(256, 1) void k_mma(
    const float* __restrict__ A0, const float* __restrict__ A1,
    int w0, int w1,
    const float* __restrict__ b0, const float* __restrict__ b1,
    const float* __restrict__ r1wl, const float* __restrict__ r1wr,
    int numOps, int do_relu,
    float* __restrict__ outp, int ostride, int ocols)
{
    extern __shared__ __align__(16) char smem[];
    uint32_t sb = smem_u32(smem);
    float* auxb = (float*)(smem + S_AUX);
    float* auxl = auxb + 128;
    float* auxr = auxl + 128;

    int tid = threadIdx.x;
    int wid = tid >> 5;
    int lane = tid & 31;
    int wr0 = wid * 16;
    int n0 = blockIdx.x * TILE_M;

    // aux staging (bias + rank-1 weight column)
    if (tid < 128) {
        int c = tid;
        float bs = (c < ocols) ? b0[c] : 0.f;
        if (b1 && c < ocols) bs += b1[c];
        auxb[c] = bs;
        auxl[c] = r1wl ? r1wl[(size_t)c * K1] : 0.f;
        auxr[c] = r1wr ? r1wr[(size_t)c * K1] : 0.f;
    }

    float acc[16][4];
#pragma unroll
    for (int i = 0; i < 16; i++)
#pragma unroll
        for (int j = 0; j < 4; j++) acc[i][j] = 0.f;

    // ldmatrix lane geometry
    int q = lane >> 3, r8 = lane & 7;
    uint32_t qrow = (uint32_t)((q & 1) * 8 + r8);
    uint32_t qkb = (uint32_t)((q >> 1) * 16);           // bytes: (q>>1)*8 bf16
    uint32_t a_off = (wr0 + qrow) * RS + qkb;

    for (int op = 0; op < numOps; ++op) {
        if (op) __syncthreads();
        const float* A = op ? A1 : A0;
        int widx = op ? w1 : w0;
        const __nv_bfloat16* Wh = g_Whi[widx];
        const __nv_bfloat16* Wl = g_Wlo[widx];

        // stage A: fp32 -> bf16 hi/lo, row-major, stride RS
        {
            int r = tid >> 1, half = tid & 1;
            int m = n0 + r;
            uint32_t dh = S_AHI + r * RS + half * 128;
            uint32_t dl = S_ALO + r * RS + half * 128;
            if (m < Nn) {
                const float4* a4 = (const float4*)(A + (size_t)m * STR + half * 64);
#pragma unroll
                for (int qq = 0; qq < 16; ++qq) {
                    float4 v = a4[qq];
                    __nv_bfloat16 hx = __float2bfloat16_rn(v.x);
                    __nv_bfloat16 hy = __float2bfloat16_rn(v.y);
                    __nv_bfloat16 hz = __float2bfloat16_rn(v.z);
                    __nv_bfloat16 hw = __float2bfloat16_rn(v.w);
                    uint2 hv, lv;
                    hv.x = ((u32)*(unsigned short*)&hy << 16) | *(unsigned short*)&hx;
                    hv.y = ((u32)*(unsigned short*)&hw << 16) | *(unsigned short*)&hz;
                    lv.x = cvt2(v.x - __bfloat162float(hx), v.y - __bfloat162float(hy));
                    lv.y = cvt2(v.z - __bfloat162float(hz), v.w - __bfloat162float(hw));
                    *(uint2*)(smem + dh + qq * 8) = hv;
                    *(uint2*)(smem + dl + qq * 8) = lv;
                }
            } else {
                uint2 z = make_uint2(0u, 0u);
#pragma unroll
                for (int qq = 0; qq < 16; ++qq) {
                    *(uint2*)(smem + dh + qq * 8) = z;
                    *(uint2*)(smem + dl + qq * 8) = z;
                }
            }
        }
        // stage W (already split bf16 in gmem, row-major [n][k])
        {
            int r = tid >> 1, half = tid & 1;
            const uint4* wsh = (const uint4*)(Wh + r * HD + half * 64);
            const uint4* wsl = (const uint4*)(Wl + r * HD + half * 64);
            uint32_t dh = S_WHI + r * RS + half * 128;
            uint32_t dl = S_WLO + r * RS + half * 128;
#pragma unroll
            for (int qq = 0; qq < 8; ++qq) {
                *(uint4*)(smem + dh + qq * 16) = wsh[qq];
                *(uint4*)(smem + dl + qq * 16) = wsl[qq];
            }
        }
        __syncthreads();

        // compute: 8 k-steps of 16
#pragma unroll
        for (int ks = 0; ks < 8; ++ks) {
            uint32_t kb = ks * 32;
            u32 ah[4], al[4];
            LDM4(ah, sb + S_AHI + a_off + kb);
            LDM4(al, sb + S_ALO + a_off + kb);
#pragma unroll
            for (int p = 0; p < 8; ++p) {
                uint32_t boff = (p * 16 + qrow) * RS + qkb + kb;
                u32 bh[4], bl[4];
                LDM4(bh, sb + S_WHI + boff);
                LDM4(bl, sb + S_WLO + boff);
                MMA(acc[2 * p],     ah, bh[0], bh[2]);
                MMA(acc[2 * p],     ah, bl[0], bl[2]);
                MMA(acc[2 * p],     al, bh[0], bh[2]);
                MMA(acc[2 * p + 1], ah, bh[1], bh[3]);
                MMA(acc[2 * p + 1], ah, bl[1], bl[3]);
                MMA(acc[2 * p + 1], al, bh[1], bh[3]);
            }
        }
    }

    // epilogue
    int l4 = lane >> 2, c2 = (lane & 3) * 2;
    int rA = n0 + wr0 + l4;
    int rB = rA + 8;
    float mcA = 0.f, scA = 0.f, mcB = 0.f, scB = 0.f;
    if (r1wl) {
        if (rA < Nn) { mcA = g_sum[(size_t)rA * STR + 128]; scA = A1[(size_t)rA * STR + 128]; }
        if (rB < Nn) { mcB = g_sum[(size_t)rB * STR + 128]; scB = A1[(size_t)rB * STR + 128]; }
    }
#pragma unroll
    for (int nt = 0; nt < 16; ++nt) {
        int c = nt * 8 + c2;
        float f0 = acc[nt][0] + auxb[c]     + mcA * auxl[c]     + scA * auxr[c];
        float f1 = acc[nt][1] + auxb[c + 1] + mcA * auxl[c + 1] + scA * auxr[c + 1];
        float f2 = acc[nt][2] + auxb[c]     + mcB * auxl[c]     + scB * auxr[c];
        float f3 = acc[nt][3] + auxb[c + 1] + mcB * auxl[c + 1] + scB * auxr[c + 1];
        if (do_relu) {
            f0 = fmaxf(f0, 0.f); f1 = fmaxf(f1, 0.f);
            f2 = fmaxf(f2, 0.f); f3 = fmaxf(f3, 0.f);
        }
        if (ocols == HD) {
            if (rA < Nn) *(float2*)(outp + (size_t)rA * ostride + c) = make_float2(f0, f1);
            if (rB < Nn) *(float2*)(outp + (size_t)rB * ostride + c) = make_float2(f2, f3);
        } else {
            if (rA < Nn) {
                if (c < ocols)     outp[(size_t)rA * ostride + c]     = f0;
                if (c + 1 < ocols) outp[(size_t)rA * ostride + c + 1] = f1;
            }
            if (rB < Nn) {
                if (c < ocols)     outp[(size_t)rB * ostride + c]     = f2;
                if (c + 1 < ocols) outp[(size_t)rB * ostride + c + 1] = f3;
            }
        }
    }
}

// ---------------- launch ----------------
extern "C" void kernel_launch(void* const* d_in, const int* in_sizes, int n_in,
                              void* d_out, int out_size) {
    int ix = 0, iWl1 = 1, ibl1 = 2, iWr1 = 3, ibr1 = 4, iWl2 = 5, ibl2 = 6,
        iWr2 = 7, ibr2 = 8, iWo = 9, ibo = 10, iei = 11, icards = 12;
    if (n_in == 13) {
        int w1a[2] = {-1, -1}; int n_w1 = 0;
        int w2a[2] = {-1, -1}; int n_w2 = 0;
        int ba[4] = {-1, -1, -1, -1}; int n_b = 0;
        int f_x = -1, f_Wo = -1, f_bo = -1, f_ei = -1, f_cards = -1;
        for (int i = 0; i < n_in; i++) {
            switch (in_sizes[i]) {
                case (int)((size_t)Nn * FIN): f_x = i; break;
                case HD * K1: if (n_w1 < 2) w1a[n_w1++] = i; break;
                case HD * HD: if (n_w2 < 2) w2a[n_w2++] = i; break;
                case HD:      if (n_b < 4)  ba[n_b++]  = i; break;
                case NCARDS * HD: f_Wo = i; break;
                case NCARDS:      f_bo = i; break;
                case 2 * Ee:      f_ei = i; break;
                case Nn:          f_cards = i; break;
                default: break;
            }
        }
        if (f_x >= 0 && n_w1 == 2 && n_w2 == 2 && n_b == 4 && f_Wo >= 0 &&
            f_bo >= 0 && f_ei >= 0 && f_cards >= 0) {
            ix = f_x; iWl1 = w1a[0]; iWr1 = w1a[1]; iWl2 = w2a[0]; iWr2 = w2a[1];
            ibl1 = ba[0]; ibr1 = ba[1]; ibl2 = ba[2]; ibr2 = ba[3];
            iWo = f_Wo; ibo = f_bo; iei = f_ei; icards = f_cards;
        }
    }

    const float* x   = (const float*)d_in[ix];
    const float* Wl1 = (const float*)d_in[iWl1];
    const float* bl1 = (const float*)d_in[ibl1];
    const float* Wr1 = (const float*)d_in[iWr1];
    const float* br1 = (const float*)d_in[ibr1];
    const float* Wl2 = (const float*)d_in[iWl2];
    const float* bl2 = (const float*)d_in[ibl2];
    const float* Wr2 = (const float*)d_in[iWr2];
    const float* br2 = (const float*)d_in[ibr2];
    const float* Wo  = (const float*)d_in[iWo];
    const float* bo  = (const float*)d_in[ibo];
    const int* ei    = (const int*)d_in[iei];
    const int* cards = (const int*)d_in[icards];
    float* out = (float*)d_out;

    cudaFuncSetAttribute(k_mma, cudaFuncAttributeMaxDynamicSharedMemorySize, SMEM_DYN);

    float *p_h0, *p_h1, *p_h2, *p_sum;
    cudaGetSymbolAddress((void**)&p_h0, g_h0);
    cudaGetSymbolAddress((void**)&p_h1, g_h1);
    cudaGetSymbolAddress((void**)&p_h2, g_h2);
    cudaGetSymbolAddress((void**)&p_sum, g_sum);

    k_detect<<<1, 1>>>(ei);
    k_init<<<(Nn + 255) / 256, 256>>>();
    k_prep_w<<<(5 * HD * HD + 255) / 256, 256>>>(Wl1, Wr1, Wl2, Wr2, Wo);
    k_concat<<<(Nn * 32 + 255) / 256, 256>>>(x, cards);

    k_deghist<<<(Ee + 255) / 256, 256>>>(ei);
    k_scan1<<<SCAN_NB, 1024>>>();
    k_scan2<<<1, 128>>>();
    k_scan3<<<(Nn + 255) / 256, 256>>>();
    k_place<<<(Ee + 255) / 256, 256>>>(ei);

    k_gather<<<2048, 256>>>(0);
    k_mma<<<NTILES, 256, SMEM_DYN>>>(p_sum, p_h0, 0, 1, bl1, br1,
                                     Wl1 + 128, Wr1 + 128, 2, 1, p_h1, STR, HD);

    k_gather<<<2048, 256>>>(1);
    k_mma<<<NTILES, 256, SMEM_DYN>>>(p_sum, p_h1, 2, 3, bl2, br2,
                                     nullptr, nullptr, 2, 1, p_h2, STR, HD);

    k_mma<<<NTILES, 256, SMEM_DYN>>>(p_h2, nullptr, 4, 4, bo, nullptr,
                                     nullptr, nullptr, 1, 0, out, NCARDS, NCARDS);
}

// round 7
// speedup vs baseline: 1.1618x; 1.0070x over previous
#include <cuda_runtime.h>
#include <cuda_bf16.h>
#include <cstdint>

#define Nn 100000
#define Ee 1600000
#define FIN 128
#define K1 129
#define HD 128
#define NCARDS 110
#define STR 132
#define SCAN_NB 98
#define TILE_M 128
#define NTILES ((Nn + TILE_M - 1) / TILE_M)   // 782

typedef unsigned int u32;

// ---------------- device scratch ----------------
__device__ float g_h0[(size_t)Nn * STR];   // fp32 (gather input, layer1); col128 = cards
__device__ float g_h1[(size_t)Nn * STR];   // fp32 (gather input, layer2)
// split-bf16 feature copies, row-major [n][128]
__device__ __nv_bfloat16 g_b0h[(size_t)Nn * HD], g_b0l[(size_t)Nn * HD];
__device__ __nv_bfloat16 g_b1h[(size_t)Nn * HD], g_b1l[(size_t)Nn * HD];
__device__ __nv_bfloat16 g_b2h[(size_t)Nn * HD], g_b2l[(size_t)Nn * HD];
__device__ __nv_bfloat16 g_bsh[(size_t)Nn * HD], g_bsl[(size_t)Nn * HD]; // mean-agg
__device__ float g_meanC[Nn];              // mean of card column (layer1 rank-1)
// bf16 split weights: 0=Wl1,1=Wr1,2=Wl2,3=Wr2,4=Wo  (padded [128,128], row-major [n][k])
__device__ __nv_bfloat16 g_Whi[5][HD * HD];
__device__ __nv_bfloat16 g_Wlo[5][HD * HD];
__device__ int g_degc[Nn];
__device__ int g_cnt[Nn];
__device__ int g_scan[Nn];
__device__ int g_offs[Nn];
__device__ int g_btot[SCAN_NB];
__device__ int g_boff[SCAN_NB];
__device__ int g_csrc[Ee];
__device__ int g_is64;

// ---------------- helpers ----------------
__device__ __forceinline__ unsigned load_ei(const int* p, size_t i, int is64) {
    if (is64) return (unsigned)((const long long*)p)[i];
    return (unsigned)p[i];
}
__device__ __forceinline__ uint32_t smem_u32(const void* p) {
    uint32_t a;
    asm("{ .reg .u64 t; cvta.to.shared.u64 t, %1; cvt.u32.u64 %0, t; }" : "=r"(a) : "l"(p));
    return a;
}
__device__ __forceinline__ u32 cvt2(float a, float b) {
    __nv_bfloat162 t = __floats2bfloat162_rn(a, b);
    return *(u32*)&t;
}
// split pair (f0,f1) -> hi u32, lo u32
__device__ __forceinline__ void split2(float f0, float f1, u32& hw, u32& lw) {
    __nv_bfloat16 h0 = __float2bfloat16_rn(f0);
    __nv_bfloat16 h1 = __float2bfloat16_rn(f1);
    hw = ((u32)*(unsigned short*)&h1 << 16) | *(unsigned short*)&h0;
    lw = cvt2(f0 - __bfloat162float(h0), f1 - __bfloat162float(h1));
}

#define LDM4(r, addr) \
    asm volatile("ldmatrix.sync.aligned.m8n8.x4.shared.b16 {%0,%1,%2,%3}, [%4];" \
                 : "=r"((r)[0]), "=r"((r)[1]), "=r"((r)[2]), "=r"((r)[3]) : "r"(addr))

#define MMA(c, a, bb0, bb1) \
    asm volatile("mma.sync.aligned.m16n8k16.row.col.f32.bf16.bf16.f32 " \
                 "{%0,%1,%2,%3},{%4,%5,%6,%7},{%8,%9},{%0,%1,%2,%3};" \
                 : "+f"((c)[0]), "+f"((c)[1]), "+f"((c)[2]), "+f"((c)[3]) \
                 : "r"((a)[0]), "r"((a)[1]), "r"((a)[2]), "r"((a)[3]), "r"(bb0), "r"(bb1))

#define CPA(dst, src) \
    asm volatile("cp.async.cg.shared.global [%0], [%1], 16;" :: "r"(dst), "l"(src))
#define CPA_COMMIT() asm volatile("cp.async.commit_group;" ::: "memory")
#define CPA_WAIT()   asm volatile("cp.async.wait_group 0;" ::: "memory")

// smem layout; row stride 272B = 17*16 -> conflict-free ldmatrix
#define RS 272
#define S_AHI 0
#define S_ALO 34816
#define S_WHI 69632
#define S_WLO 87040
#define S_AUX 104448            // auxb[64], auxl[64], auxr[64] floats
#define SMEM_DYN (104448 + 3 * 64 * 4)

// ---------------- setup (+dtype detect) ----------------
__global__ void k_init(const int* __restrict__ ei32) {
    int i = blockIdx.x * blockDim.x + threadIdx.x;
    if (i < Nn) { g_degc[i] = 0; g_cnt[i] = 0; }
    if (i == 0) {
        int all_zero = 1;
        for (int w = 1; w < 64; w += 2)
            if (ei32[w] != 0) { all_zero = 0; break; }
        g_is64 = all_zero;
    }
}

__global__ void k_prep_w(const float* __restrict__ Wl1, const float* __restrict__ Wr1,
                         const float* __restrict__ Wl2, const float* __restrict__ Wr2,
                         const float* __restrict__ Wo) {
    int i = blockIdx.x * blockDim.x + threadIdx.x;
    if (i >= 5 * HD * HD) return;
    int op = i / (HD * HD);
    int r = i % (HD * HD);
    int n = r / HD, k = r % HD;
    float v = 0.f;
    if (op == 0) v = Wl1[n * K1 + k];
    else if (op == 1) v = Wr1[n * K1 + k];
    else if (op == 2) v = Wl2[n * HD + k];
    else if (op == 3) v = Wr2[n * HD + k];
    else if (n < NCARDS) v = Wo[n * HD + k];
    __nv_bfloat16 h = __float2bfloat16_rn(v);
    g_Whi[op][r] = h;
    g_Wlo[op][r] = __float2bfloat16_rn(v - __bfloat162float(h));
}

__global__ void k_concat(const float* __restrict__ x, const int* __restrict__ cards) {
    int i = blockIdx.x * blockDim.x + threadIdx.x;
    if (i >= Nn * 32) return;
    int n = i >> 5, c = (i & 31) * 4;
    float4 v = *(const float4*)(x + (size_t)n * FIN + c);
    *(float4*)(g_h0 + (size_t)n * STR + c) = v;
    uint2 hv, lv;
    split2(v.x, v.y, hv.x, lv.x);
    split2(v.z, v.w, hv.y, lv.y);
    *(uint2*)(g_b0h + (size_t)n * HD + c) = hv;
    *(uint2*)(g_b0l + (size_t)n * HD + c) = lv;
    if ((i & 31) == 0)
        *(float4*)(g_h0 + (size_t)n * STR + 128) = make_float4((float)cards[n], 0.f, 0.f, 0.f);
}

// ---------------- CSR build ----------------
__global__ void k_deghist(const int* __restrict__ ei) {
    int e = blockIdx.x * blockDim.x + threadIdx.x;
    if (e < Ee) {
        unsigned d = load_ei(ei, (size_t)Ee + e, g_is64);
        if (d < Nn) atomicAdd(&g_degc[d], 1);
    }
}

__global__ void k_scan1() {
    __shared__ int sh[1024];
    int b = blockIdx.x, t = threadIdx.x;
    int n = b * 1024 + t;
    int v = (n < Nn) ? g_degc[n] : 0;
    sh[t] = v;
    __syncthreads();
    for (int off = 1; off < 1024; off <<= 1) {
        int add = (t >= off) ? sh[t - off] : 0;
        __syncthreads();
        sh[t] += add;
        __syncthreads();
    }
    if (n < Nn) g_scan[n] = sh[t];
    if (t == 1023) g_btot[b] = sh[t];
}

__global__ void k_scan2() {
    __shared__ int sh[128];
    int t = threadIdx.x;
    int v = (t < SCAN_NB) ? g_btot[t] : 0;
    sh[t] = v;
    __syncthreads();
    for (int off = 1; off < 128; off <<= 1) {
        int add = (t >= off) ? sh[t - off] : 0;
        __syncthreads();
        sh[t] += add;
        __syncthreads();
    }
    if (t < SCAN_NB) g_boff[t] = sh[t] - v;
}

__global__ void k_scan3() {
    int n = blockIdx.x * blockDim.x + threadIdx.x;
    if (n < Nn) g_offs[n] = g_scan[n] - g_degc[n] + g_boff[n >> 10];
}

__global__ void k_place(const int* __restrict__ ei) {
    int e = blockIdx.x * blockDim.x + threadIdx.x;
    if (e < Ee) {
        int is64 = g_is64;
        unsigned s = load_ei(ei, (size_t)e, is64);
        unsigned d = load_ei(ei, (size_t)Ee + e, is64);
        if (s < Nn && d < Nn) {
            int pos = g_offs[d] + atomicAdd(&g_cnt[d], 1);
            if (pos >= 0 && pos < Ee) g_csrc[pos] = (int)s;
        }
    }
}

// ---------------- gather mean-aggregation; writes split bf16 ----------------
__global__ void k_gather(int layer) {
    const float* __restrict__ h = layer ? g_h1 : g_h0;
    int gw = (blockIdx.x * blockDim.x + threadIdx.x) >> 5;
    int lane = threadIdx.x & 31;
    int nw = (gridDim.x * blockDim.x) >> 5;
    for (int n = gw; n < Nn; n += nw) {
        int st = g_offs[n];
        int dg = g_degc[n];
        if (st < 0) st = 0;
        if (st + dg > Ee) dg = Ee - st;
        float4 acc = make_float4(0.f, 0.f, 0.f, 0.f);
        float accC = 0.f;
        int sNext = (dg > 0) ? g_csrc[st] : 0;
        for (int i = 0; i < dg; ++i) {
            int s = sNext;
            if (i + 1 < dg) sNext = g_csrc[st + i + 1];
            const float* row = h + (size_t)s * STR;
            float4 v = *(const float4*)(row + lane * 4);
            acc.x += v.x; acc.y += v.y; acc.z += v.z; acc.w += v.w;
            if (layer == 0 && lane == 0) accC += row[128];
        }
        float di = (dg > 0) ? 1.f / (float)dg : 0.f;
        acc.x *= di; acc.y *= di; acc.z *= di; acc.w *= di;
        uint2 hv, lv;
        split2(acc.x, acc.y, hv.x, lv.x);
        split2(acc.z, acc.w, hv.y, lv.y);
        *(uint2*)(g_bsh + (size_t)n * HD + lane * 4) = hv;
        *(uint2*)(g_bsl + (size_t)n * HD + lane * 4) = lv;
        if (layer == 0 && lane == 0) g_meanC[n] = accC * di;
    }
}

// ---------------- HMMA fused layer (TILE 128m x 64n) ----------------
__global__ __launch_bounds__(256, 2) void k_mma(
    const __nv_bfloat16* __restrict__ A0h, const __nv_bfloat16* __restrict__ A0l,
    const __nv_bfloat16* __restrict__ A1h, const __nv_bfloat16* __restrict__ A1l,
    int w0, int w1,
    const float* __restrict__ b0, const float* __restrict__ b1,
    const float* __restrict__ r1wl, const float* __restrict__ r1wr,
    const float* __restrict__ fself,   // fp32 features (col128 = self card), rank-1 only
    int numOps, int do_relu,
    float* __restrict__ fout, int ostride, int ocols,
    __nv_bfloat16* __restrict__ bh_out, __nv_bfloat16* __restrict__ bl_out)
{
    extern __shared__ __align__(16) char smem[];
    uint32_t sb = smem_u32(smem);
    float* auxb = (float*)(smem + S_AUX);
    float* auxl = auxb + 64;
    float* auxr = auxl + 64;

    int tid = threadIdx.x;
    int wid = tid >> 5;
    int lane = tid & 31;
    int wr0 = wid * 16;
    int n0 = blockIdx.x * TILE_M;
    int c_base = blockIdx.y * 64;

    if (tid < 64) {
        int cg = c_base + tid;
        float bs = (cg < ocols) ? b0[cg] : 0.f;
        if (b1 && cg < ocols) bs += b1[cg];
        auxb[tid] = bs;
        auxl[tid] = r1wl ? r1wl[(size_t)cg * K1] : 0.f;
        auxr[tid] = r1wr ? r1wr[(size_t)cg * K1] : 0.f;
    }

    float acc[8][4];
#pragma unroll
    for (int i = 0; i < 8; i++)
#pragma unroll
        for (int j = 0; j < 4; j++) acc[i][j] = 0.f;

    int q = lane >> 3, r8 = lane & 7;
    uint32_t qrow = (uint32_t)((q & 1) * 8 + r8);
    uint32_t qkb = (uint32_t)((q >> 1) * 16);
    uint32_t a_off = (wr0 + qrow) * RS + qkb;

    for (int op = 0; op < numOps; ++op) {
        if (op) __syncthreads();
        const __nv_bfloat16* Ah = op ? A1h : A0h;
        const __nv_bfloat16* Al = op ? A1l : A0l;
        const __nv_bfloat16* Wh = g_Whi[op ? w1 : w0];
        const __nv_bfloat16* Wl = g_Wlo[op ? w1 : w0];

        // stage A: pure 16B async copies
        {
            int r = tid >> 1, half = tid & 1;
            int m = n0 + r;
            uint32_t dh = sb + S_AHI + r * RS + half * 128;
            uint32_t dl = sb + S_ALO + r * RS + half * 128;
            if (m < Nn) {
                const char* srch = (const char*)(Ah + (size_t)m * HD + half * 64);
                const char* srcl = (const char*)(Al + (size_t)m * HD + half * 64);
#pragma unroll
                for (int qq = 0; qq < 8; ++qq) {
                    CPA(dh + qq * 16, srch + qq * 16);
                    CPA(dl + qq * 16, srcl + qq * 16);
                }
            } else {
                uint4 z = make_uint4(0, 0, 0, 0);
#pragma unroll
                for (int qq = 0; qq < 8; ++qq) {
                    *(uint4*)(smem + S_AHI + r * RS + half * 128 + qq * 16) = z;
                    *(uint4*)(smem + S_ALO + r * RS + half * 128 + qq * 16) = z;
                }
            }
        }
        // stage W (64 rows of this col-half)
        {
            int r = tid >> 2, qtr = tid & 3;
            int nrow = c_base + r;
            const char* srch = (const char*)(Wh + (size_t)nrow * HD + qtr * 32);
            const char* srcl = (const char*)(Wl + (size_t)nrow * HD + qtr * 32);
            uint32_t dh = sb + S_WHI + r * RS + qtr * 64;
            uint32_t dl = sb + S_WLO + r * RS + qtr * 64;
#pragma unroll
            for (int qq = 0; qq < 4; ++qq) {
                CPA(dh + qq * 16, srch + qq * 16);
                CPA(dl + qq * 16, srcl + qq * 16);
            }
        }
        CPA_COMMIT();
        CPA_WAIT();
        __syncthreads();

#pragma unroll
        for (int ks = 0; ks < 8; ++ks) {
            uint32_t kb = ks * 32;
            u32 ah[4], al[4];
            LDM4(ah, sb + S_AHI + a_off + kb);
            LDM4(al, sb + S_ALO + a_off + kb);
#pragma unroll
            for (int p = 0; p < 4; ++p) {
                uint32_t boff = (p * 16 + qrow) * RS + qkb + kb;
                u32 bh[4], bl[4];
                LDM4(bh, sb + S_WHI + boff);
                LDM4(bl, sb + S_WLO + boff);
                MMA(acc[2 * p],     ah, bh[0], bh[2]);
                MMA(acc[2 * p],     ah, bl[0], bl[2]);
                MMA(acc[2 * p],     al, bh[0], bh[2]);
                MMA(acc[2 * p + 1], ah, bh[1], bh[3]);
                MMA(acc[2 * p + 1], ah, bl[1], bl[3]);
                MMA(acc[2 * p + 1], al, bh[1], bh[3]);
            }
        }
    }

    // epilogue
    int l4 = lane >> 2, c2 = (lane & 3) * 2;
    int rA = n0 + wr0 + l4;
    int rB = rA + 8;
    float mcA = 0.f, scA = 0.f, mcB = 0.f, scB = 0.f;
    if (r1wl) {
        if (rA < Nn) { mcA = g_meanC[rA]; scA = fself[(size_t)rA * STR + 128]; }
        if (rB < Nn) { mcB = g_meanC[rB]; scB = fself[(size_t)rB * STR + 128]; }
    }
#pragma unroll
    for (int nt = 0; nt < 8; ++nt) {
        int c = nt * 8 + c2;           // local col in [0,64)
        int gc = c_base + c;           // global col
        float f0 = acc[nt][0] + auxb[c]     + mcA * auxl[c]     + scA * auxr[c];
        float f1 = acc[nt][1] + auxb[c + 1] + mcA * auxl[c + 1] + scA * auxr[c + 1];
        float f2 = acc[nt][2] + auxb[c]     + mcB * auxl[c]     + scB * auxr[c];
        float f3 = acc[nt][3] + auxb[c + 1] + mcB * auxl[c + 1] + scB * auxr[c + 1];
        if (do_relu) {
            f0 = fmaxf(f0, 0.f); f1 = fmaxf(f1, 0.f);
            f2 = fmaxf(f2, 0.f); f3 = fmaxf(f3, 0.f);
        }
        if (fout) {
            if (ocols == HD) {
                if (rA < Nn) *(float2*)(fout + (size_t)rA * ostride + gc) = make_float2(f0, f1);
                if (rB < Nn) *(float2*)(fout + (size_t)rB * ostride + gc) = make_float2(f2, f3);
            } else {
                if (rA < Nn) {
                    if (gc < ocols)     fout[(size_t)rA * ostride + gc]     = f0;
                    if (gc + 1 < ocols) fout[(size_t)rA * ostride + gc + 1] = f1;
                }
                if (rB < Nn) {
                    if (gc < ocols)     fout[(size_t)rB * ostride + gc]     = f2;
                    if (gc + 1 < ocols) fout[(size_t)rB * ostride + gc + 1] = f3;
                }
            }
        }
        if (bh_out) {
            u32 hw, lw;
            if (rA < Nn) {
                split2(f0, f1, hw, lw);
                *(u32*)(bh_out + (size_t)rA * HD + gc) = hw;
                *(u32*)(bl_out + (size_t)rA * HD + gc) = lw;
            }
            if (rB < Nn) {
                split2(f2, f3, hw, lw);
                *(u32*)(bh_out + (size_t)rB * HD + gc) = hw;
                *(u32*)(bl_out + (size_t)rB * HD + gc) = lw;
            }
        }
    }
}

// ---------------- launch ----------------
extern "C" void kernel_launch(void* const* d_in, const int* in_sizes, int n_in,
                              void* d_out, int out_size) {
    int ix = 0, iWl1 = 1, ibl1 = 2, iWr1 = 3, ibr1 = 4, iWl2 = 5, ibl2 = 6,
        iWr2 = 7, ibr2 = 8, iWo = 9, ibo = 10, iei = 11, icards = 12;
    if (n_in == 13) {
        int w1a[2] = {-1, -1}; int n_w1 = 0;
        int w2a[2] = {-1, -1}; int n_w2 = 0;
        int ba[4] = {-1, -1, -1, -1}; int n_b = 0;
        int f_x = -1, f_Wo = -1, f_bo = -1, f_ei = -1, f_cards = -1;
        for (int i = 0; i < n_in; i++) {
            switch (in_sizes[i]) {
                case (int)((size_t)Nn * FIN): f_x = i; break;
                case HD * K1: if (n_w1 < 2) w1a[n_w1++] = i; break;
                case HD * HD: if (n_w2 < 2) w2a[n_w2++] = i; break;
                case HD:      if (n_b < 4)  ba[n_b++]  = i; break;
                case NCARDS * HD: f_Wo = i; break;
                case NCARDS:      f_bo = i; break;
                case 2 * Ee:      f_ei = i; break;
                case Nn:          f_cards = i; break;
                default: break;
            }
        }
        if (f_x >= 0 && n_w1 == 2 && n_w2 == 2 && n_b == 4 && f_Wo >= 0 &&
            f_bo >= 0 && f_ei >= 0 && f_cards >= 0) {
            ix = f_x; iWl1 = w1a[0]; iWr1 = w1a[1]; iWl2 = w2a[0]; iWr2 = w2a[1];
            ibl1 = ba[0]; ibr1 = ba[1]; ibl2 = ba[2]; ibr2 = ba[3];
            iWo = f_Wo; ibo = f_bo; iei = f_ei; icards = f_cards;
        }
    }

    const float* x   = (const float*)d_in[ix];
    const float* Wl1 = (const float*)d_in[iWl1];
    const float* bl1 = (const float*)d_in[ibl1];
    const float* Wr1 = (const float*)d_in[iWr1];
    const float* br1 = (const float*)d_in[ibr1];
    const float* Wl2 = (const float*)d_in[iWl2];
    const float* bl2 = (const float*)d_in[ibl2];
    const float* Wr2 = (const float*)d_in[iWr2];
    const float* br2 = (const float*)d_in[ibr2];
    const float* Wo  = (const float*)d_in[iWo];
    const float* bo  = (const float*)d_in[ibo];
    const int* ei    = (const int*)d_in[iei];
    const int* cards = (const int*)d_in[icards];
    float* out = (float*)d_out;

    cudaFuncSetAttribute(k_mma, cudaFuncAttributeMaxDynamicSharedMemorySize, SMEM_DYN);

    float *p_h0, *p_h1;
    __nv_bfloat16 *p_b0h, *p_b0l, *p_b1h, *p_b1l, *p_b2h, *p_b2l, *p_bsh, *p_bsl;
    cudaGetSymbolAddress((void**)&p_h0, g_h0);
    cudaGetSymbolAddress((void**)&p_h1, g_h1);
    cudaGetSymbolAddress((void**)&p_b0h, g_b0h);
    cudaGetSymbolAddress((void**)&p_b0l, g_b0l);
    cudaGetSymbolAddress((void**)&p_b1h, g_b1h);
    cudaGetSymbolAddress((void**)&p_b1l, g_b1l);
    cudaGetSymbolAddress((void**)&p_b2h, g_b2h);
    cudaGetSymbolAddress((void**)&p_b2l, g_b2l);
    cudaGetSymbolAddress((void**)&p_bsh, g_bsh);
    cudaGetSymbolAddress((void**)&p_bsl, g_bsl);

    dim3 mg(NTILES, 2);

    k_init<<<(Nn + 255) / 256, 256>>>(ei);
    k_prep_w<<<(5 * HD * HD + 255) / 256, 256>>>(Wl1, Wr1, Wl2, Wr2, Wo);
    k_concat<<<(Nn * 32 + 255) / 256, 256>>>(x, cards);

    k_deghist<<<(Ee + 255) / 256, 256>>>(ei);
    k_scan1<<<SCAN_NB, 1024>>>();
    k_scan2<<<1, 128>>>();
    k_scan3<<<(Nn + 255) / 256, 256>>>();
    k_place<<<(Ee + 255) / 256, 256>>>(ei);

    k_gather<<<2048, 256>>>(0);
    k_mma<<<mg, 256, SMEM_DYN>>>(p_bsh, p_bsl, p_b0h, p_b0l, 0, 1, bl1, br1,
                                 Wl1 + 128, Wr1 + 128, p_h0, 2, 1,
                                 p_h1, STR, HD, p_b1h, p_b1l);

    k_gather<<<2048, 256>>>(1);
    k_mma<<<mg, 256, SMEM_DYN>>>(p_bsh, p_bsl, p_b1h, p_b1l, 2, 3, bl2, br2,
                                 nullptr, nullptr, nullptr, 2, 1,
                                 nullptr, 0, HD, p_b2h, p_b2l);

    k_mma<<<mg, 256, SMEM_DYN>>>(p_b2h, p_b2l, nullptr, nullptr, 4, 4, bo, nullptr,
                                 nullptr, nullptr, nullptr, 1, 0,
                                 out, NCARDS, NCARDS, nullptr, nullptr);
}